// round 1
// baseline (speedup 1.0000x reference)
#include <cuda_runtime.h>
#include <math.h>

#define N_RES 8192
#define N_IN  128
#define BATCH 16
#define LEAK  0.9f

// Scratch (allocation-free: __device__ globals).
// Transposed layouts: [row][batch], 64B per row -> coalesced v4 access.
__device__ __align__(16) float g_z[N_RES * BATCH];        // 512 KB accumulator
__device__ __align__(16) float g_state_T[N_RES * BATCH];  // 512 KB, L2-resident
__device__ __align__(16) float g_x_T[N_IN * BATCH];       // 8 KB

__device__ __forceinline__ void red_add_v4(float* p, float a, float b, float c, float d) {
    asm volatile("red.global.add.v4.f32 [%0], {%1,%2,%3,%4};"
                 :: "l"(p), "f"(a), "f"(b), "f"(c), "f"(d) : "memory");
}

// ---------------------------------------------------------------------------
// Kernel 1: init z with biases, transpose state and x into [row][batch].
__global__ void k_init(const float* __restrict__ state,
                       const float* __restrict__ x,
                       const float* __restrict__ res_bias,
                       const float* __restrict__ in_bias) {
    int i = blockIdx.x * blockDim.x + threadIdx.x;
    if (i < N_RES * BATCH) {
        int r = i >> 4;        // i / BATCH
        int b = i & (BATCH - 1);
        g_z[i]       = res_bias[r] + in_bias[r];
        g_state_T[i] = state[b * N_RES + r];
    }
    if (i < N_IN * BATCH) {
        int r = i >> 4;
        int b = i & (BATCH - 1);
        g_x_T[i] = x[b * N_IN + r];
    }
}

// ---------------------------------------------------------------------------
// Kernel 2: input SpMM (small, 104857 entries).
__global__ void k_in_spmm(const float* __restrict__ vals,
                          const int*   __restrict__ rows,
                          const int*   __restrict__ cols,
                          int nnz) {
    int i = blockIdx.x * blockDim.x + threadIdx.x;
    if (i >= nnz) return;
    float v = vals[i];
    int r = rows[i];
    int c = cols[i];
    const float4* s = reinterpret_cast<const float4*>(g_x_T + c * BATCH);
    float4 s0 = s[0], s1 = s[1], s2 = s[2], s3 = s[3];
    float* zp = g_z + r * BATCH;
    red_add_v4(zp + 0,  v * s0.x, v * s0.y, v * s0.z, v * s0.w);
    red_add_v4(zp + 4,  v * s1.x, v * s1.y, v * s1.z, v * s1.w);
    red_add_v4(zp + 8,  v * s2.x, v * s2.y, v * s2.z, v * s2.w);
    red_add_v4(zp + 12, v * s3.x, v * s3.y, v * s3.z, v * s3.w);
}

// ---------------------------------------------------------------------------
// Kernel 3: reservoir SpMM (dominant: 6.71M entries x 16 batches).
// Per entry: 12B coalesced stream read (DRAM), 64B gather (L2-resident state_T),
// 16 FMA, 4 x red.global.add.v4.f32 (L2 RMW).
__global__ void __launch_bounds__(256) k_res_spmm(const float* __restrict__ vals,
                                                  const int*   __restrict__ rows,
                                                  const int*   __restrict__ cols,
                                                  int nnz) {
    int i = blockIdx.x * blockDim.x + threadIdx.x;
    if (i >= nnz) return;
    float v = vals[i];
    int r = rows[i];
    int c = cols[i];
    const float4* s = reinterpret_cast<const float4*>(g_state_T + c * BATCH);
    float4 s0 = s[0], s1 = s[1], s2 = s[2], s3 = s[3];
    float* zp = g_z + r * BATCH;
    red_add_v4(zp + 0,  v * s0.x, v * s0.y, v * s0.z, v * s0.w);
    red_add_v4(zp + 4,  v * s1.x, v * s1.y, v * s1.z, v * s1.w);
    red_add_v4(zp + 8,  v * s2.x, v * s2.y, v * s2.z, v * s2.w);
    red_add_v4(zp + 12, v * s3.x, v * s3.y, v * s3.z, v * s3.w);
}

// ---------------------------------------------------------------------------
// Kernel 4: epilogue  out[b,r] = (1-LEAK)*state[b,r] + LEAK*erf(z[r,b])
__global__ void k_epilogue(const float* __restrict__ state,
                           float* __restrict__ out) {
    int i = blockIdx.x * blockDim.x + threadIdx.x;  // b-major over [BATCH, N_RES]
    if (i >= BATCH * N_RES) return;
    int b = i >> 13;           // i / N_RES
    int r = i & (N_RES - 1);
    float z = g_z[r * BATCH + b];
    out[i] = (1.0f - LEAK) * state[i] + LEAK * erff(z);
}

// ---------------------------------------------------------------------------
extern "C" void kernel_launch(void* const* d_in, const int* in_sizes, int n_in,
                              void* d_out, int out_size) {
    const float* state    = (const float*)d_in[0];
    const float* x        = (const float*)d_in[1];
    const float* res_vals = (const float*)d_in[2];
    const int*   res_rows = (const int*)  d_in[3];
    const int*   res_cols = (const int*)  d_in[4];
    const float* res_bias = (const float*)d_in[5];
    const float* in_vals  = (const float*)d_in[6];
    const int*   in_rows  = (const int*)  d_in[7];
    const int*   in_cols  = (const int*)  d_in[8];
    const float* in_bias  = (const float*)d_in[9];
    float* out = (float*)d_out;

    int res_nnz = in_sizes[2];
    int in_nnz  = in_sizes[6];

    int n_init = N_RES * BATCH;
    k_init<<<(n_init + 255) / 256, 256>>>(state, x, res_bias, in_bias);

    k_in_spmm<<<(in_nnz + 255) / 256, 256>>>(in_vals, in_rows, in_cols, in_nnz);

    k_res_spmm<<<(res_nnz + 255) / 256, 256>>>(res_vals, res_rows, res_cols, res_nnz);

    k_epilogue<<<(BATCH * N_RES + 255) / 256, 256>>>(state, out);
}